// round 1
// baseline (speedup 1.0000x reference)
#include <cuda_runtime.h>
#include <math.h>

#define BB 8
#define NN 2048
#define FIN 512
#define FOUT 256
#define ALPHA 0.2f

// Scratch (allocation-free rule: __device__ globals)
__device__ float g_Wh[BB * NN * FOUT];   // 16.8 MB
__device__ float g_f1[BB * NN];
__device__ float g_f2[BB * NN];

// ---------------------------------------------------------------------------
// Kernel 1: Wh = h @ W   (M=16384, K=512, N=256), fp32 tiled SGEMM
// Block tile 128x64, BK=16, 256 threads, thread tile 8x4.
// ---------------------------------------------------------------------------
__global__ __launch_bounds__(256) void wh_gemm(const float* __restrict__ h,
                                               const float* __restrict__ W) {
    __shared__ float As[16][132];  // [k][m], padded vs bank conflicts
    __shared__ float Bs[16][68];   // [k][n], padded

    const int tid  = threadIdx.x;
    const int row0 = blockIdx.y * 128;
    const int col0 = blockIdx.x * 64;
    const int tx   = tid & 15;   // 16 col-groups of 4
    const int ty   = tid >> 4;   // 16 row-groups of 8

    float acc[8][4];
#pragma unroll
    for (int r = 0; r < 8; r++)
#pragma unroll
        for (int c = 0; c < 4; c++) acc[r][c] = 0.f;

    for (int k0 = 0; k0 < FIN; k0 += 16) {
        // Load A tile 128x16 (transposed into As[k][m])
#pragma unroll
        for (int it = 0; it < 2; it++) {
            int idx = tid + 256 * it;
            int r = idx >> 2, c4 = idx & 3;
            float4 v = *(const float4*)&h[(size_t)(row0 + r) * FIN + k0 + c4 * 4];
            As[c4 * 4 + 0][r] = v.x;
            As[c4 * 4 + 1][r] = v.y;
            As[c4 * 4 + 2][r] = v.z;
            As[c4 * 4 + 3][r] = v.w;
        }
        // Load B tile 16x64
        {
            int kk = tid >> 4, c4 = tid & 15;
            *(float4*)&Bs[kk][c4 * 4] =
                *(const float4*)&W[(size_t)(k0 + kk) * FOUT + col0 + c4 * 4];
        }
        __syncthreads();

#pragma unroll
        for (int k = 0; k < 16; k++) {
            float4 a0 = *(float4*)&As[k][ty * 8];
            float4 a1 = *(float4*)&As[k][ty * 8 + 4];
            float4 b0 = *(float4*)&Bs[k][tx * 4];
            float ar[8] = {a0.x, a0.y, a0.z, a0.w, a1.x, a1.y, a1.z, a1.w};
            float br[4] = {b0.x, b0.y, b0.z, b0.w};
#pragma unroll
            for (int r = 0; r < 8; r++)
#pragma unroll
                for (int c = 0; c < 4; c++) acc[r][c] += ar[r] * br[c];
        }
        __syncthreads();
    }

#pragma unroll
    for (int r = 0; r < 8; r++) {
        int row = row0 + ty * 8 + r;
        float4 o = make_float4(acc[r][0], acc[r][1], acc[r][2], acc[r][3]);
        *(float4*)&g_Wh[(size_t)row * FOUT + col0 + tx * 4] = o;
    }
}

// ---------------------------------------------------------------------------
// Kernel 2: f1/f2 = Wh @ a1, Wh @ a2. One warp per row.
// ---------------------------------------------------------------------------
__global__ __launch_bounds__(256) void f_kernel(const float* __restrict__ a) {
    int gwarp = (blockIdx.x * blockDim.x + threadIdx.x) >> 5;
    int lane  = threadIdx.x & 31;
    if (gwarp >= BB * NN) return;
    const float* wh = &g_Wh[(size_t)gwarp * FOUT];
    float s1 = 0.f, s2 = 0.f;
#pragma unroll
    for (int u = 0; u < 8; u++) {
        float v = wh[lane + 32 * u];
        s1 += v * a[lane + 32 * u];
        s2 += v * a[FOUT + lane + 32 * u];
    }
#pragma unroll
    for (int off = 16; off; off >>= 1) {
        s1 += __shfl_xor_sync(0xFFFFFFFFu, s1, off);
        s2 += __shfl_xor_sync(0xFFFFFFFFu, s2, off);
    }
    if (lane == 0) {
        g_f1[gwarp] = s1;
        g_f2[gwarp] = s2;
    }
}

// ---------------------------------------------------------------------------
// Kernel 3: fused masked-softmax attention aggregation + ELU.
// Block = (b, 32-row i-tile). Streams j in tiles of 32:
//   w_ij = adj ? exp(leakyrelu(f1_i + f2_j)) : 0   (no max-sub needed: |e|<~15)
//   acc  += w_tile(32x32) @ Wh_tile(32x256)
//   den_i += sum_j w_ij
// Epilogue: out = elu(acc / den).
// ---------------------------------------------------------------------------
__global__ __launch_bounds__(256, 4) void attn_kernel(const int* __restrict__ adj,
                                                      float* __restrict__ out) {
    __shared__ float Wh_s[32][256];  // 32 KB
    __shared__ float w_s[32][36];    // [j-within-tile][i-row], padded
    __shared__ float f1_s[32];
    __shared__ float den_s[32];

    const int b   = blockIdx.y;
    const int i0  = blockIdx.x * 32;
    const int tid = threadIdx.x;
    const int tx  = tid & 31;  // col group: 8 consecutive cols at tx*8
    const int ty  = tid >> 5;  // row group: 4 rows at ty*4

    if (tid < 32) {
        f1_s[tid] = g_f1[b * NN + i0 + tid];
        den_s[tid] = 0.f;
    }

    float acc[4][8];
#pragma unroll
    for (int r = 0; r < 4; r++)
#pragma unroll
        for (int c = 0; c < 8; c++) acc[r][c] = 0.f;

    const int*   adj_b = adj + (size_t)b * NN * NN;
    const float* Wh_b  = g_Wh + (size_t)b * NN * FOUT;
    const float* f2_b  = g_f2 + b * NN;

    __syncthreads();

    for (int j0 = 0; j0 < NN; j0 += 32) {
        // --- compute w tile (each thread: 4 consecutive j of one i-row) ---
        {
            int e = tid * 4;
            int r = e >> 5, c = e & 31;
            int4  av  = *(const int4*)&adj_b[(size_t)(i0 + r) * NN + j0 + c];
            float f1v = f1_s[r];
            int   am[4] = {av.x, av.y, av.z, av.w};
            float wsum = 0.f;
#pragma unroll
            for (int u = 0; u < 4; u++) {
                float s = f1v + f2_b[j0 + c + u];
                s = s > 0.f ? s : ALPHA * s;
                float w = (am[u] > 0) ? __expf(s) : 0.f;
                w_s[c + u][r] = w;
                wsum += w;
            }
            atomicAdd(&den_s[r], wsum);
        }
        // --- load Wh tile 32x256 ---
#pragma unroll
        for (int it = 0; it < 8; it++) {
            int idx = tid + 256 * it;
            int r = idx >> 6, c4 = idx & 63;
            *(float4*)&Wh_s[r][c4 * 4] =
                *(const float4*)&Wh_b[(size_t)(j0 + r) * FOUT + c4 * 4];
        }
        __syncthreads();

        // --- outer product: acc(4x8) += w(4) * Wh(8) over k=0..31 ---
#pragma unroll 8
        for (int k = 0; k < 32; k++) {
            float4 wv = *(float4*)&w_s[k][ty * 4];           // broadcast per warp
            float4 h0 = *(float4*)&Wh_s[k][tx * 8];
            float4 h1 = *(float4*)&Wh_s[k][tx * 8 + 4];
            float wr[4] = {wv.x, wv.y, wv.z, wv.w};
            float hr[8] = {h0.x, h0.y, h0.z, h0.w, h1.x, h1.y, h1.z, h1.w};
#pragma unroll
            for (int r = 0; r < 4; r++)
#pragma unroll
                for (int c = 0; c < 8; c++) acc[r][c] += wr[r] * hr[c];
        }
        __syncthreads();  // protect w_s / Wh_s before next tile overwrite
    }

    // --- epilogue: divide by denominator, ELU, store ---
#pragma unroll
    for (int r = 0; r < 4; r++) {
        int   row = i0 + ty * 4 + r;
        float inv = 1.f / den_s[ty * 4 + r];
        float o[8];
#pragma unroll
        for (int c = 0; c < 8; c++) {
            float x = acc[r][c] * inv;
            o[c] = x > 0.f ? x : expm1f(x);
        }
        float4* dst = (float4*)&out[((size_t)b * NN + row) * FOUT + tx * 8];
        dst[0] = make_float4(o[0], o[1], o[2], o[3]);
        dst[1] = make_float4(o[4], o[5], o[6], o[7]);
    }
}

// ---------------------------------------------------------------------------
extern "C" void kernel_launch(void* const* d_in, const int* in_sizes, int n_in,
                              void* d_out, int out_size) {
    const float* h   = (const float*)d_in[0];
    const int*   adj = (const int*)d_in[1];
    const float* W   = (const float*)d_in[2];
    const float* a   = (const float*)d_in[3];
    float*       out = (float*)d_out;

    wh_gemm<<<dim3(FOUT / 64, (BB * NN) / 128), 256>>>(h, W);
    f_kernel<<<(BB * NN) / 8, 256>>>(a);
    attn_kernel<<<dim3(NN / 32, BB), 256>>>(adj, out);
}

// round 3
// speedup vs baseline: 2.5561x; 2.5561x over previous
#include <cuda_runtime.h>
#include <math.h>
#include <stdint.h>

#define BB 8
#define NN 2048
#define FIN 512
#define FOUT 256
#define ALPHA 0.2f

// Scratch (allocation-free rule: __device__ globals)
__device__ float g_Wh[BB * NN * FOUT];   // [b][j][n]
__device__ float g_f1[BB * NN];
__device__ float g_f2[BB * NN];

// ---------------------------------------------------------------------------
// Kernel 1: Wh = h @ W   (M=16384, K=512, N=256), fp32 tiled SGEMM (exact)
// ---------------------------------------------------------------------------
__global__ __launch_bounds__(256) void wh_gemm(const float* __restrict__ h,
                                               const float* __restrict__ W) {
    __shared__ float As[16][132];
    __shared__ float Bs[16][68];

    const int tid  = threadIdx.x;
    const int row0 = blockIdx.y * 128;
    const int col0 = blockIdx.x * 64;
    const int tx   = tid & 15;
    const int ty   = tid >> 4;

    float acc[8][4];
#pragma unroll
    for (int r = 0; r < 8; r++)
#pragma unroll
        for (int c = 0; c < 4; c++) acc[r][c] = 0.f;

    for (int k0 = 0; k0 < FIN; k0 += 16) {
#pragma unroll
        for (int it = 0; it < 2; it++) {
            int idx = tid + 256 * it;
            int r = idx >> 2, c4 = idx & 3;
            float4 v = *(const float4*)&h[(size_t)(row0 + r) * FIN + k0 + c4 * 4];
            As[c4 * 4 + 0][r] = v.x;
            As[c4 * 4 + 1][r] = v.y;
            As[c4 * 4 + 2][r] = v.z;
            As[c4 * 4 + 3][r] = v.w;
        }
        {
            int kk = tid >> 4, c4 = tid & 15;
            *(float4*)&Bs[kk][c4 * 4] =
                *(const float4*)&W[(size_t)(k0 + kk) * FOUT + col0 + c4 * 4];
        }
        __syncthreads();
#pragma unroll
        for (int k = 0; k < 16; k++) {
            float4 a0 = *(float4*)&As[k][ty * 8];
            float4 a1 = *(float4*)&As[k][ty * 8 + 4];
            float4 b0 = *(float4*)&Bs[k][tx * 4];
            float ar[8] = {a0.x, a0.y, a0.z, a0.w, a1.x, a1.y, a1.z, a1.w};
            float br[4] = {b0.x, b0.y, b0.z, b0.w};
#pragma unroll
            for (int r = 0; r < 8; r++)
#pragma unroll
                for (int c = 0; c < 4; c++) acc[r][c] += ar[r] * br[c];
        }
        __syncthreads();
    }

#pragma unroll
    for (int r = 0; r < 8; r++) {
        int row = row0 + ty * 8 + r;
        float4 o = make_float4(acc[r][0], acc[r][1], acc[r][2], acc[r][3]);
        *(float4*)&g_Wh[(size_t)row * FOUT + col0 + tx * 4] = o;
    }
}

// ---------------------------------------------------------------------------
// Kernel 2: f1/f2 = Wh @ a1, Wh @ a2 (fp32 exact)
// ---------------------------------------------------------------------------
__global__ __launch_bounds__(256) void f_kernel(const float* __restrict__ a) {
    int gwarp = (blockIdx.x * blockDim.x + threadIdx.x) >> 5;
    int lane  = threadIdx.x & 31;
    if (gwarp >= BB * NN) return;
    const float* wh = &g_Wh[(size_t)gwarp * FOUT];
    float s1 = 0.f, s2 = 0.f;
#pragma unroll
    for (int u = 0; u < 8; u++) {
        float v = wh[lane + 32 * u];
        s1 += v * a[lane + 32 * u];
        s2 += v * a[FOUT + lane + 32 * u];
    }
#pragma unroll
    for (int off = 16; off; off >>= 1) {
        s1 += __shfl_xor_sync(0xFFFFFFFFu, s1, off);
        s2 += __shfl_xor_sync(0xFFFFFFFFu, s2, off);
    }
    if (lane == 0) {
        g_f1[gwarp] = s1;
        g_f2[gwarp] = s2;
    }
}

// ---------------------------------------------------------------------------
// mma.sync m16n8k8 tf32 (legacy tensor-core path — PTX target-safe)
// ---------------------------------------------------------------------------
__device__ __forceinline__ void mma_tf32(float d[4], const uint32_t a[4],
                                         const uint32_t b[2]) {
    asm volatile(
        "mma.sync.aligned.m16n8k8.row.col.f32.tf32.tf32.f32 "
        "{%0,%1,%2,%3}, {%4,%5,%6,%7}, {%8,%9}, {%0,%1,%2,%3};"
        : "+f"(d[0]), "+f"(d[1]), "+f"(d[2]), "+f"(d[3])
        : "r"(a[0]), "r"(a[1]), "r"(a[2]), "r"(a[3]), "r"(b[0]), "r"(b[1]));
}
__device__ __forceinline__ uint32_t to_tf32(float x) {
    uint32_t r;
    asm("cvt.rna.tf32.f32 %0, %1;" : "=r"(r) : "f"(x));
    return r;
}

// ---------------------------------------------------------------------------
// Kernel 3: fused masked-softmax aggregation on tensor cores (tf32 mma.sync).
// Block: 512 threads, output tile 128(i) x 256(n). Warps 4m x 4n, warp tile
// 32x64 (2 m-frags x 8 n-frags of m16n8). Streams j in tiles of 32 (4 k-frags).
//   smem: w tile [128][36] (tf32 bits), Wh tile [32][264] (tf32 bits, pad
//   stride 264 -> conflict-free B-frag LDS), f2 row, f1, den.
// Grid = 16 x 8 = 128 blocks = single wave.
// ---------------------------------------------------------------------------
#define SM_WH   0            // 32*264 = 8448 floats
#define SM_W    8448         // 128*36 = 4608
#define SM_F2   13056        // 2048
#define SM_F1   15104        // 128
#define SM_DEN  15232        // 128
#define ATTN_SMEM_F 15360    // floats -> 61440 bytes

__global__ __launch_bounds__(512, 1) void attn_mma(const int* __restrict__ adj,
                                                   float* __restrict__ out) {
    extern __shared__ float smem[];
    float* Wh_s = smem + SM_WH;
    float* w_s  = smem + SM_W;
    float* f2s  = smem + SM_F2;
    float* f1s  = smem + SM_F1;
    float* dens = smem + SM_DEN;

    const int tid  = threadIdx.x;
    const int warp = tid >> 5;
    const int lane = tid & 31;
    const int mw   = warp >> 2;           // 0..3 -> m-rows mw*32
    const int nw   = warp & 3;            // 0..3 -> n-cols nw*64
    const int g    = lane >> 2;           // 0..7
    const int t    = lane & 3;            // 0..3
    const int b    = blockIdx.y;
    const int i0   = blockIdx.x * 128;

    // Stage f2 (full row) and f1 (this i-tile)
    {
        const float4* f2g = (const float4*)(g_f2 + b * NN);
        ((float4*)f2s)[tid] = f2g[tid];   // 512 * 4 = 2048
        if (tid < 128) f1s[tid] = g_f1[b * NN + i0 + tid];
    }

    // w-fill mapping: each thread owns row r, 8 consecutive j at jq*8
    const int   r   = tid >> 2;
    const int   jq  = tid & 3;
    const int*  arow = adj + ((size_t)(b * NN + i0 + r)) * NN + jq * 8;

    float acc[2][8][4];
#pragma unroll
    for (int fm = 0; fm < 2; fm++)
#pragma unroll
        for (int fn = 0; fn < 8; fn++)
#pragma unroll
            for (int c = 0; c < 4; c++) acc[fm][fn][c] = 0.f;

    __syncthreads();
    const float f1v = f1s[r];
    float den = 0.f;

    for (int tt = 0; tt < 64; tt++) {
        const int j0 = tt * 32;

        // --- fill w tile (tf32-rounded; den uses identical values) ---
        {
            int4 av0 = *(const int4*)(arow + j0);
            int4 av1 = *(const int4*)(arow + j0 + 4);
            int  am[8] = {av0.x, av0.y, av0.z, av0.w, av1.x, av1.y, av1.z, av1.w};
            float* wrow = w_s + r * 36 + jq * 8;
            const float* f2p = f2s + j0 + jq * 8;
#pragma unroll
            for (int u = 0; u < 8; u++) {
                float e = f1v + f2p[u];
                e = e > 0.f ? e : ALPHA * e;
                float w = (am[u] > 0) ? __expf(e) : 0.f;
                float wv = __uint_as_float(to_tf32(w));
                wrow[u] = wv;
                den += wv;
            }
        }
        // --- fill Wh tile 32 x 256 (tf32-rounded), stride 264 ---
        {
            const float* src = g_Wh + ((size_t)(b * NN + j0)) * FOUT;
#pragma unroll
            for (int p = 0; p < 4; p++) {
                int idx = tid + 512 * p;
                int row = idx >> 6, c4 = idx & 63;
                float4 v = *(const float4*)&src[(size_t)row * FOUT + c4 * 4];
                float4 o;
                o.x = __uint_as_float(to_tf32(v.x));
                o.y = __uint_as_float(to_tf32(v.y));
                o.z = __uint_as_float(to_tf32(v.z));
                o.w = __uint_as_float(to_tf32(v.w));
                *(float4*)&Wh_s[row * 264 + c4 * 4] = o;
            }
        }
        __syncthreads();

        // --- tensor-core tile: 4 k-frags of K=8 ---
#pragma unroll
        for (int fk = 0; fk < 4; fk++) {
            uint32_t A[2][4];
#pragma unroll
            for (int fm = 0; fm < 2; fm++) {
                const float* wa = w_s + (mw * 32 + fm * 16 + g) * 36 + fk * 8 + t;
                A[fm][0] = __float_as_uint(wa[0]);
                A[fm][1] = __float_as_uint(wa[8 * 36]);
                A[fm][2] = __float_as_uint(wa[4]);
                A[fm][3] = __float_as_uint(wa[8 * 36 + 4]);
            }
#pragma unroll
            for (int fn = 0; fn < 8; fn++) {
                uint32_t Bf[2];
                const float* wb = Wh_s + (fk * 8 + t) * 264 + nw * 64 + fn * 8 + g;
                Bf[0] = __float_as_uint(wb[0]);
                Bf[1] = __float_as_uint(wb[4 * 264]);
                mma_tf32(acc[0][fn], A[0], Bf);
                mma_tf32(acc[1][fn], A[1], Bf);
            }
        }
        __syncthreads();
    }

    // --- denominator: reduce 4 threads per row (consecutive lanes) ---
    den += __shfl_xor_sync(0xFFFFFFFFu, den, 1);
    den += __shfl_xor_sync(0xFFFFFFFFu, den, 2);
    if (jq == 0) dens[r] = den;
    __syncthreads();

    // --- epilogue: /den, ELU, store (float2 per c-pair) ---
#pragma unroll
    for (int fm = 0; fm < 2; fm++) {
        int row0 = mw * 32 + fm * 16 + g;
        float inv0 = 1.f / dens[row0];
        float inv1 = 1.f / dens[row0 + 8];
        float* o0 = out + ((size_t)(b * NN + i0 + row0)) * FOUT;
        float* o1 = out + ((size_t)(b * NN + i0 + row0 + 8)) * FOUT;
#pragma unroll
        for (int fn = 0; fn < 8; fn++) {
            int col = nw * 64 + fn * 8 + t * 2;
            float x0 = acc[fm][fn][0] * inv0;
            float x1 = acc[fm][fn][1] * inv0;
            float x2 = acc[fm][fn][2] * inv1;
            float x3 = acc[fm][fn][3] * inv1;
            float2 v0, v1;
            v0.x = x0 > 0.f ? x0 : expm1f(x0);
            v0.y = x1 > 0.f ? x1 : expm1f(x1);
            v1.x = x2 > 0.f ? x2 : expm1f(x2);
            v1.y = x3 > 0.f ? x3 : expm1f(x3);
            *(float2*)&o0[col] = v0;
            *(float2*)&o1[col] = v1;
        }
    }
}

// ---------------------------------------------------------------------------
extern "C" void kernel_launch(void* const* d_in, const int* in_sizes, int n_in,
                              void* d_out, int out_size) {
    const float* h   = (const float*)d_in[0];
    const int*   adj = (const int*)d_in[1];
    const float* W   = (const float*)d_in[2];
    const float* a   = (const float*)d_in[3];
    float*       out = (float*)d_out;

    cudaFuncSetAttribute(attn_mma, cudaFuncAttributeMaxDynamicSharedMemorySize,
                         ATTN_SMEM_F * 4);

    wh_gemm<<<dim3(FOUT / 64, (BB * NN) / 128), 256>>>(h, W);
    f_kernel<<<(BB * NN) / 8, 256>>>(a);
    attn_mma<<<dim3(NN / 128, BB), 512, ATTN_SMEM_F * 4>>>(adj, out);
}

// round 4
// speedup vs baseline: 3.7800x; 1.4788x over previous
#include <cuda_runtime.h>
#include <math.h>
#include <stdint.h>

#define BB 8
#define NN 2048
#define FIN 512
#define FOUT 256
#define ALPHA 0.2f

// Scratch (allocation-free rule: __device__ globals)
__device__ float  g_Wh[BB * NN * FOUT];  // [b][j][n]
__device__ float  g_f1[BB * NN];
__device__ float  g_f2[BB * NN];
__device__ float2 g_e1[BB * NN];         // {exp(f1), exp(ALPHA*f1)}
__device__ float2 g_e2[BB * NN];         // {exp(f2), exp(ALPHA*f2)}

// ---------------------------------------------------------------------------
// mma.sync m16n8k8 tf32 helpers (legacy tensor path — PTX target-safe)
// ---------------------------------------------------------------------------
__device__ __forceinline__ void mma_tf32(float d[4], const uint32_t a[4],
                                         const uint32_t b[2]) {
    asm volatile(
        "mma.sync.aligned.m16n8k8.row.col.f32.tf32.tf32.f32 "
        "{%0,%1,%2,%3}, {%4,%5,%6,%7}, {%8,%9}, {%0,%1,%2,%3};"
        : "+f"(d[0]), "+f"(d[1]), "+f"(d[2]), "+f"(d[3])
        : "r"(a[0]), "r"(a[1]), "r"(a[2]), "r"(a[3]), "r"(b[0]), "r"(b[1]));
}
__device__ __forceinline__ uint32_t to_tf32(float x) {
    uint32_t r;
    asm("cvt.rna.tf32.f32 %0, %1;" : "=r"(r) : "f"(x));
    return r;
}

// ---------------------------------------------------------------------------
// Kernel 1: Wh = h @ W on tensor cores (tf32). Block 512 thr, tile 128m x 256n,
// warps 4m x 4n (warp tile 32x64), K streamed in tiles of 32. Grid 128 = 1 wave.
// ---------------------------------------------------------------------------
#define WG_AS 0                 // A_s [128][36]
#define WG_BS (128 * 36)        // B_s [32][264]
#define WG_SMEM_F (128 * 36 + 32 * 264)

__global__ __launch_bounds__(512, 1) void wh_tc(const float* __restrict__ h,
                                                const float* __restrict__ W) {
    extern __shared__ float sm[];
    float* A_s = sm + WG_AS;
    float* B_s = sm + WG_BS;

    const int tid  = threadIdx.x;
    const int warp = tid >> 5;
    const int lane = tid & 31;
    const int mw   = warp >> 2;
    const int nw   = warp & 3;
    const int g    = lane >> 2;
    const int t    = lane & 3;
    const int row0 = blockIdx.x * 128;

    float acc[2][8][4];
#pragma unroll
    for (int fm = 0; fm < 2; fm++)
#pragma unroll
        for (int fn = 0; fn < 8; fn++)
#pragma unroll
            for (int c = 0; c < 4; c++) acc[fm][fn][c] = 0.f;

    const int r = tid >> 2, q = tid & 3;   // A-fill: row r, k-cols q*8..q*8+7

    for (int k0 = 0; k0 < FIN; k0 += 32) {
        // --- A tile: h[row0..+128][k0..+32], tf32-rounded ---
        {
            const float* src = h + (size_t)(row0 + r) * FIN + k0 + q * 8;
            float4 v0 = *(const float4*)src;
            float4 v1 = *(const float4*)(src + 4);
            float* dst = A_s + r * 36 + q * 8;
            dst[0] = __uint_as_float(to_tf32(v0.x));
            dst[1] = __uint_as_float(to_tf32(v0.y));
            dst[2] = __uint_as_float(to_tf32(v0.z));
            dst[3] = __uint_as_float(to_tf32(v0.w));
            dst[4] = __uint_as_float(to_tf32(v1.x));
            dst[5] = __uint_as_float(to_tf32(v1.y));
            dst[6] = __uint_as_float(to_tf32(v1.z));
            dst[7] = __uint_as_float(to_tf32(v1.w));
        }
        // --- B tile: W[k0..+32][0..256], tf32-rounded, stride 264 ---
#pragma unroll
        for (int p = 0; p < 4; p++) {
            int idx = tid + 512 * p;
            int row = idx >> 6, c4 = idx & 63;
            float4 v = *(const float4*)&W[(size_t)(k0 + row) * FOUT + c4 * 4];
            float4 o;
            o.x = __uint_as_float(to_tf32(v.x));
            o.y = __uint_as_float(to_tf32(v.y));
            o.z = __uint_as_float(to_tf32(v.z));
            o.w = __uint_as_float(to_tf32(v.w));
            *(float4*)&B_s[row * 264 + c4 * 4] = o;
        }
        __syncthreads();

#pragma unroll
        for (int fk = 0; fk < 4; fk++) {
            uint32_t A[2][4];
#pragma unroll
            for (int fm = 0; fm < 2; fm++) {
                const float* wa = A_s + (mw * 32 + fm * 16 + g) * 36 + fk * 8 + t;
                A[fm][0] = __float_as_uint(wa[0]);
                A[fm][1] = __float_as_uint(wa[8 * 36]);
                A[fm][2] = __float_as_uint(wa[4]);
                A[fm][3] = __float_as_uint(wa[8 * 36 + 4]);
            }
#pragma unroll
            for (int fn = 0; fn < 8; fn++) {
                uint32_t Bf[2];
                const float* wb = B_s + (fk * 8 + t) * 264 + nw * 64 + fn * 8 + g;
                Bf[0] = __float_as_uint(wb[0]);
                Bf[1] = __float_as_uint(wb[4 * 264]);
                mma_tf32(acc[0][fn], A[0], Bf);
                mma_tf32(acc[1][fn], A[1], Bf);
            }
        }
        __syncthreads();
    }

#pragma unroll
    for (int fm = 0; fm < 2; fm++) {
        int rr = row0 + mw * 32 + fm * 16 + g;
        float* o0 = g_Wh + (size_t)rr * FOUT;
        float* o1 = g_Wh + (size_t)(rr + 8) * FOUT;
#pragma unroll
        for (int fn = 0; fn < 8; fn++) {
            int col = nw * 64 + fn * 8 + t * 2;
            *(float2*)&o0[col] = make_float2(acc[fm][fn][0], acc[fm][fn][1]);
            *(float2*)&o1[col] = make_float2(acc[fm][fn][2], acc[fm][fn][3]);
        }
    }
}

// ---------------------------------------------------------------------------
// Kernel 2: f1/f2 + the 4 exp tables (kills the 33.6M-exp MUFU bottleneck)
// ---------------------------------------------------------------------------
__global__ __launch_bounds__(256) void f_kernel(const float* __restrict__ a) {
    int gwarp = (blockIdx.x * blockDim.x + threadIdx.x) >> 5;
    int lane  = threadIdx.x & 31;
    if (gwarp >= BB * NN) return;
    const float* wh = &g_Wh[(size_t)gwarp * FOUT];
    float s1 = 0.f, s2 = 0.f;
#pragma unroll
    for (int u = 0; u < 8; u++) {
        float v = wh[lane + 32 * u];
        s1 += v * a[lane + 32 * u];
        s2 += v * a[FOUT + lane + 32 * u];
    }
#pragma unroll
    for (int off = 16; off; off >>= 1) {
        s1 += __shfl_xor_sync(0xFFFFFFFFu, s1, off);
        s2 += __shfl_xor_sync(0xFFFFFFFFu, s2, off);
    }
    if (lane == 0) {
        g_f1[gwarp] = s1;
        g_f2[gwarp] = s2;
        g_e1[gwarp] = make_float2(__expf(s1), __expf(ALPHA * s1));
        g_e2[gwarp] = make_float2(__expf(s2), __expf(ALPHA * s2));
    }
}

// ---------------------------------------------------------------------------
// Kernel 3: fused masked-softmax aggregation, tf32 mma.sync, exp-free w-fill.
//   w_ij = adj ? ((f1+f2>0) ? e1p_i*e2p_j : e1n_i*e2n_j) : 0
// Block 512 thr, out tile 128 x 256, j streamed in tiles of 32. Grid 16x8 = 1 wave.
// ---------------------------------------------------------------------------
#define SM_WH   0                      // 32*264  = 8448
#define SM_W    8448                   // 128*36  = 4608
#define SM_F2   13056                  // 2048
#define SM_E2   15104                  // float2[2048] = 4096
#define SM_F1   19200                  // 128
#define SM_DEN  19328                  // 128
#define ATTN_SMEM_F 19456              // 77824 bytes

__global__ __launch_bounds__(512, 1) void attn_mma(const int* __restrict__ adj,
                                                   float* __restrict__ out) {
    extern __shared__ float smem[];
    float*  Wh_s = smem + SM_WH;
    float*  w_s  = smem + SM_W;
    float*  f2s  = smem + SM_F2;
    float2* e2s  = (float2*)(smem + SM_E2);
    float*  f1s  = smem + SM_F1;
    float*  dens = smem + SM_DEN;

    const int tid  = threadIdx.x;
    const int warp = tid >> 5;
    const int lane = tid & 31;
    const int mw   = warp >> 2;
    const int nw   = warp & 3;
    const int g    = lane >> 2;
    const int t    = lane & 3;
    const int b    = blockIdx.y;
    const int i0   = blockIdx.x * 128;

    // Stage f2, e2 (full row), f1 (tile)
    {
        const float4* f2g = (const float4*)(g_f2 + b * NN);
        ((float4*)f2s)[tid] = f2g[tid];
        const float4* e2g = (const float4*)(g_e2 + b * NN);
        ((float4*)e2s)[tid]       = e2g[tid];
        ((float4*)e2s)[tid + 512] = e2g[tid + 512];
        if (tid < 128) f1s[tid] = g_f1[b * NN + i0 + tid];
    }

    const int    r    = tid >> 2;   // i-row this thread fills (4 thr/row)
    const int    jq   = tid & 3;    // 8 consecutive j at jq*8
    const int4*  arow = (const int4*)(adj + ((size_t)(b * NN + i0 + r)) * NN + jq * 8);
    const float2 e1   = g_e1[b * NN + i0 + r];

    float acc[2][8][4];
#pragma unroll
    for (int fm = 0; fm < 2; fm++)
#pragma unroll
        for (int fn = 0; fn < 8; fn++)
#pragma unroll
            for (int c = 0; c < 4; c++) acc[fm][fn][c] = 0.f;

    __syncthreads();
    const float f1v = f1s[r];
    float den = 0.f;

    // adj prefetch for tile 0 (int4 pair = 8 ints)
    int4 av0 = arow[0];
    int4 av1 = arow[1];

    for (int tt = 0; tt < 64; tt++) {
        const int j0 = tt * 32;

        // --- w tile fill: exp-free, tf32-rounded (den uses identical values) ---
        {
            int am[8] = {av0.x, av0.y, av0.z, av0.w, av1.x, av1.y, av1.z, av1.w};
            float* wrow = w_s + r * 36 + jq * 8;
            const float*  f2p = f2s + j0 + jq * 8;
            const float2* e2p = e2s + j0 + jq * 8;
#pragma unroll
            for (int u = 0; u < 8; u++) {
                float  e  = f1v + f2p[u];
                float2 e2 = e2p[u];
                float  w  = (e > 0.f) ? e1.x * e2.x : e1.y * e2.y;
                w = (am[u] > 0) ? w : 0.f;
                float wv = __uint_as_float(to_tf32(w));
                wrow[u] = wv;
                den += wv;
            }
        }
        // prefetch next tile's adj (completes under this tile's mma phase)
        if (tt < 63) {
            av0 = arow[(tt + 1) * 8];
            av1 = arow[(tt + 1) * 8 + 1];
        }
        // --- Wh tile 32 x 256 (tf32-rounded), stride 264 ---
        {
            const float* src = g_Wh + ((size_t)(b * NN + j0)) * FOUT;
#pragma unroll
            for (int p = 0; p < 4; p++) {
                int idx = tid + 512 * p;
                int row = idx >> 6, c4 = idx & 63;
                float4 v = *(const float4*)&src[(size_t)row * FOUT + c4 * 4];
                float4 o;
                o.x = __uint_as_float(to_tf32(v.x));
                o.y = __uint_as_float(to_tf32(v.y));
                o.z = __uint_as_float(to_tf32(v.z));
                o.w = __uint_as_float(to_tf32(v.w));
                *(float4*)&Wh_s[row * 264 + c4 * 4] = o;
            }
        }
        __syncthreads();

#pragma unroll
        for (int fk = 0; fk < 4; fk++) {
            uint32_t A[2][4];
#pragma unroll
            for (int fm = 0; fm < 2; fm++) {
                const float* wa = w_s + (mw * 32 + fm * 16 + g) * 36 + fk * 8 + t;
                A[fm][0] = __float_as_uint(wa[0]);
                A[fm][1] = __float_as_uint(wa[8 * 36]);
                A[fm][2] = __float_as_uint(wa[4]);
                A[fm][3] = __float_as_uint(wa[8 * 36 + 4]);
            }
#pragma unroll
            for (int fn = 0; fn < 8; fn++) {
                uint32_t Bf[2];
                const float* wb = Wh_s + (fk * 8 + t) * 264 + nw * 64 + fn * 8 + g;
                Bf[0] = __float_as_uint(wb[0]);
                Bf[1] = __float_as_uint(wb[4 * 264]);
                mma_tf32(acc[0][fn], A[0], Bf);
                mma_tf32(acc[1][fn], A[1], Bf);
            }
        }
        __syncthreads();
    }

    // --- denominator: reduce 4 threads per row ---
    den += __shfl_xor_sync(0xFFFFFFFFu, den, 1);
    den += __shfl_xor_sync(0xFFFFFFFFu, den, 2);
    if (jq == 0) dens[r] = den;
    __syncthreads();

    // --- epilogue: /den, ELU, store ---
#pragma unroll
    for (int fm = 0; fm < 2; fm++) {
        int row0 = mw * 32 + fm * 16 + g;
        float inv0 = 1.f / dens[row0];
        float inv1 = 1.f / dens[row0 + 8];
        float* o0 = out + ((size_t)(b * NN + i0 + row0)) * FOUT;
        float* o1 = out + ((size_t)(b * NN + i0 + row0 + 8)) * FOUT;
#pragma unroll
        for (int fn = 0; fn < 8; fn++) {
            int col = nw * 64 + fn * 8 + t * 2;
            float x0 = acc[fm][fn][0] * inv0;
            float x1 = acc[fm][fn][1] * inv0;
            float x2 = acc[fm][fn][2] * inv1;
            float x3 = acc[fm][fn][3] * inv1;
            float2 v0, v1;
            v0.x = x0 > 0.f ? x0 : expm1f(x0);
            v0.y = x1 > 0.f ? x1 : expm1f(x1);
            v1.x = x2 > 0.f ? x2 : expm1f(x2);
            v1.y = x3 > 0.f ? x3 : expm1f(x3);
            *(float2*)&o0[col] = v0;
            *(float2*)&o1[col] = v1;
        }
    }
}

// ---------------------------------------------------------------------------
extern "C" void kernel_launch(void* const* d_in, const int* in_sizes, int n_in,
                              void* d_out, int out_size) {
    const float* h   = (const float*)d_in[0];
    const int*   adj = (const int*)d_in[1];
    const float* W   = (const float*)d_in[2];
    const float* a   = (const float*)d_in[3];
    float*       out = (float*)d_out;

    cudaFuncSetAttribute(wh_tc, cudaFuncAttributeMaxDynamicSharedMemorySize,
                         WG_SMEM_F * 4);
    cudaFuncSetAttribute(attn_mma, cudaFuncAttributeMaxDynamicSharedMemorySize,
                         ATTN_SMEM_F * 4);

    wh_tc<<<(BB * NN) / 128, 512, WG_SMEM_F * 4>>>(h, W);
    f_kernel<<<(BB * NN) / 8, 256>>>(a);
    attn_mma<<<dim3(NN / 128, BB), 512, ATTN_SMEM_F * 4>>>(adj, out);
}